// round 1
// baseline (speedup 1.0000x reference)
#include <cuda_runtime.h>
#include <math.h>

// Problem dims
#define BB   128          // batch
#define SS   256          // seq len
#define EE   512          // embed dim
#define HH   1024         // hidden
#define KTOT 1536         // E + H (concatenated GEMM K)
#define NJ   1024         // hidden columns per gate

// Tiling
#define BM   64           // batch rows per CTA
#define BJ   16           // hidden cols per CTA (x3 gates)
#define BK   32           // K tile
#define NBLK 128          // (128/BM) * (1024/BJ) = 2 * 64

// ---------------- device global scratch (no allocations allowed) ------------
// Packed transposed weights: Wp[k][gate][j], gates = {i, g, o} (f-gate is dead:
// carried cell state is always zero in the reference).
__device__ __align__(16) float g_Wp[KTOT * 3 * NJ];     // 18.9 MB
__device__ float g_biasp[3 * NJ];
__device__ __align__(16) float g_Xe[SS * BB * EE];       // gathered embeddings, 64 MB
__device__ __align__(16) float g_h[2][BB * HH];          // double-buffered hidden state
__device__ unsigned g_count;                             // barrier arrive counter (zero-init)
__device__ volatile unsigned g_gen;                      // barrier generation

// ---------------- prep: pack weights (i,g,o blocks, transposed, fused bias) --
__global__ void pack_kernel(const float* __restrict__ W_ih, const float* __restrict__ W_hh,
                            const float* __restrict__ b_ih, const float* __restrict__ b_hh) {
    const int gate_blk[3] = {0, 2, 3};   // PyTorch order i,f,g,o -> keep i,g,o
    int idx = blockIdx.x * blockDim.x + threadIdx.x;
    const int total = KTOT * 3 * NJ;
    if (idx < total) {
        int k = idx / (3 * NJ);
        int r = idx - k * 3 * NJ;
        int g = r / NJ;
        int j = r - g * NJ;
        int row = gate_blk[g] * HH + j;
        g_Wp[idx] = (k < EE) ? W_ih[row * EE + k] : W_hh[row * HH + (k - EE)];
    }
    if (idx < 3 * NJ) {
        int g = idx / NJ;
        int j = idx - g * NJ;
        int row = gate_blk[g] * HH + j;
        g_biasp[idx] = b_ih[row] + b_hh[row];
    }
}

// ---------------- prep: embedding gather  Xe[t][b][e] ------------------------
__global__ void gather_kernel(const int* __restrict__ inputs, const float* __restrict__ embed) {
    int gid = blockIdx.x * blockDim.x + threadIdx.x;   // one float4
    const int total4 = SS * BB * (EE / 4);
    if (gid >= total4) return;
    int t = gid / (BB * (EE / 4));
    int r = gid - t * (BB * (EE / 4));
    int b = r / (EE / 4);
    int q = r - b * (EE / 4);
    int tok = inputs[b * SS + t];
    reinterpret_cast<float4*>(g_Xe)[gid] =
        reinterpret_cast<const float4*>(embed)[(size_t)tok * (EE / 4) + q];
}

// ---------------- prep: zero h0 (must run every launch/replay) ---------------
__global__ void zero_h_kernel() {
    int i = blockIdx.x * blockDim.x + threadIdx.x;
    if (i < BB * HH) g_h[0][i] = 0.0f;
}

// ---------------- global barrier (sense-reversing, all CTAs resident) --------
__device__ __forceinline__ void grid_barrier() {
    __syncthreads();
    if (threadIdx.x == 0) {
        __threadfence();
        unsigned my = g_gen;                 // current generation (monotonic)
        unsigned t = atomicAdd(&g_count, 1u);
        if (t == NBLK - 1u) {
            atomicExch(&g_count, 0u);
            __threadfence();
            g_gen = my + 1u;                 // release
        } else {
            while (g_gen == my) { __nanosleep(64); }
        }
        __threadfence();
    }
    __syncthreads();
}

// ---------------- helpers: register-staged tile loads (SW pipeline) ----------
__device__ __forceinline__ void load_x_regs(float4& xr0, float4& xr1,
                                            const float* __restrict__ xe,
                                            const float* __restrict__ hprev,
                                            int k0, int m0, int ml, int kq) {
    const float* src; int stride, kk0;
    if (k0 < EE) { src = xe;    stride = EE; kk0 = k0; }
    else         { src = hprev; stride = HH; kk0 = k0 - EE; }
    const float* p = src + (size_t)(m0 + ml) * stride + kk0 + kq * 4;
    xr0 = *reinterpret_cast<const float4*>(p);
    xr1 = *reinterpret_cast<const float4*>(p + 16);
}

__device__ __forceinline__ void load_w_regs(float wr[6], int k0, int j0, int tid) {
#pragma unroll
    for (int u = 0; u < 6; ++u) {
        int i = tid + u * 256;               // 0..1535 over 32k x 48(=3*16)
        int kk = i / 48;
        int r  = i - kk * 48;                // g*16 + jj
        int g  = r >> 4;
        int jj = r & 15;
        wr[u] = g_Wp[(size_t)(k0 + kk) * (3 * NJ) + g * NJ + (j0 + jj)];
    }
}

// ---------------- persistent recurrent kernel --------------------------------
__global__ void __launch_bounds__(256, 1) lstm_kernel(float* __restrict__ out) {
    __shared__ __align__(16) float Xs[BK][BM + 4];   // stride 68 floats (16B aligned rows)
    __shared__ float Ws[BK][3 * BJ];

    const int tid = threadIdx.x;
    const int tx  = tid & 15;        // j within tile
    const int ty  = tid >> 4;        // m-group (4 rows each)
    const int j0  = blockIdx.x * BJ;
    const int m0  = blockIdx.y * BM;
    const int ml  = tid >> 2;        // loader: row 0..63
    const int kq  = tid & 3;         // loader: k quad

    const float bi = g_biasp[0 * NJ + j0 + tx];
    const float bg = g_biasp[1 * NJ + j0 + tx];
    const float bo = g_biasp[2 * NJ + j0 + tx];

    for (int t = 0; t < SS; ++t) {
        const float* __restrict__ hprev = g_h[t & 1];
        float* __restrict__ hnext = g_h[(t + 1) & 1];
        const float* __restrict__ xe = g_Xe + (size_t)t * BB * EE;

        float acc[3][4];
#pragma unroll
        for (int g = 0; g < 3; ++g)
#pragma unroll
            for (int m = 0; m < 4; ++m) acc[g][m] = 0.0f;

        // preload tile 0 (k0=0 < E: reads Xe only)
        float4 xr0, xr1;
        float wr[6];
        load_x_regs(xr0, xr1, xe, hprev, 0, m0, ml, kq);
        load_w_regs(wr, 0, j0, tid);

        for (int kt = 0; kt < KTOT / BK; ++kt) {
            __syncthreads();   // previous compute done reading smem
            // stage registers -> smem
            {
                int kb = kq * 4;
                Xs[kb + 0][ml] = xr0.x;  Xs[kb + 1][ml] = xr0.y;
                Xs[kb + 2][ml] = xr0.z;  Xs[kb + 3][ml] = xr0.w;
                Xs[kb + 16][ml] = xr1.x; Xs[kb + 17][ml] = xr1.y;
                Xs[kb + 18][ml] = xr1.z; Xs[kb + 19][ml] = xr1.w;
#pragma unroll
                for (int u = 0; u < 6; ++u) {
                    int i = tid + u * 256;
                    int kk = i / 48;
                    int r  = i - kk * 48;
                    Ws[kk][r] = wr[u];
                }
            }
            __syncthreads();
            // prefetch next tile into registers (hide L2 latency under compute)
            if (kt + 1 < KTOT / BK) {
                int k0n = (kt + 1) * BK;
                load_x_regs(xr0, xr1, xe, hprev, k0n, m0, ml, kq);
                load_w_regs(wr, k0n, j0, tid);
            }
            // compute
#pragma unroll
            for (int kk = 0; kk < BK; ++kk) {
                float4 xv = *reinterpret_cast<const float4*>(&Xs[kk][ty * 4]);
                float wi = Ws[kk][tx];
                float wg = Ws[kk][16 + tx];
                float wo = Ws[kk][32 + tx];
                acc[0][0] += xv.x * wi; acc[0][1] += xv.y * wi;
                acc[0][2] += xv.z * wi; acc[0][3] += xv.w * wi;
                acc[1][0] += xv.x * wg; acc[1][1] += xv.y * wg;
                acc[1][2] += xv.z * wg; acc[1][3] += xv.w * wg;
                acc[2][0] += xv.x * wo; acc[2][1] += xv.y * wo;
                acc[2][2] += xv.z * wo; acc[2][3] += xv.w * wo;
            }
        }

        // epilogue: h = sigmoid(o) * tanh( sigmoid(i) * tanh(g) )   (cell carry is zero)
#pragma unroll
        for (int m = 0; m < 4; ++m) {
            int row = m0 + ty * 4 + m;
            float iv = acc[0][m] + bi;
            float gv = acc[1][m] + bg;
            float ov = acc[2][m] + bo;
            float ct = (1.0f / (1.0f + expf(-iv))) * tanhf(gv);
            float hv = (1.0f / (1.0f + expf(-ov))) * tanhf(ct);
            hnext[(size_t)row * HH + j0 + tx] = hv;
            if (t == SS - 1) out[(size_t)row * HH + j0 + tx] = hv;
        }

        grid_barrier();
    }
}

// ---------------- launch -----------------------------------------------------
extern "C" void kernel_launch(void* const* d_in, const int* in_sizes, int n_in,
                              void* d_out, int out_size) {
    const int*   inputs = (const int*)  d_in[0];
    const float* embed  = (const float*)d_in[1];
    const float* W_ih   = (const float*)d_in[2];
    const float* W_hh   = (const float*)d_in[3];
    const float* b_ih   = (const float*)d_in[4];
    const float* b_hh   = (const float*)d_in[5];
    float* out = (float*)d_out;

    const int totalW = KTOT * 3 * NJ;
    pack_kernel<<<(totalW + 255) / 256, 256>>>(W_ih, W_hh, b_ih, b_hh);

    const int total4 = SS * BB * (EE / 4);
    gather_kernel<<<(total4 + 255) / 256, 256>>>(inputs, embed);

    zero_h_kernel<<<(BB * HH + 255) / 256, 256>>>();

    dim3 grid(NJ / BJ, BB / BM);   // (64, 2) = 128 CTAs, all co-resident on 148 SMs
    lstm_kernel<<<grid, 256>>>(out);
}

// round 2
// speedup vs baseline: 1.0338x; 1.0338x over previous
#include <cuda_runtime.h>
#include <math.h>

// Problem dims
#define BB   128          // batch
#define SS   256          // seq len
#define EE   512          // embed dim
#define HH   1024         // hidden
#define KTOT 1536         // E + H (concatenated GEMM K)
#define NJ   1024         // hidden columns per gate

// Tiling
#define BM   64           // batch rows per CTA
#define BJ   16           // hidden cols per CTA (x3 gates)
#define BK   32           // K tile
#define NBLK 128          // (128/BM) * (1024/BJ) = 2 * 64

// ---------------- device global scratch (no allocations allowed) ------------
// Packed transposed weights: Wp[k][gate][j], gates = {i, g, o} (f-gate is dead:
// carried cell state is always zero in the reference).
__device__ __align__(16) float g_Wp[KTOT * 3 * NJ];     // 18.9 MB
__device__ float g_biasp[3 * NJ];
__device__ __align__(16) float g_Xe[SS * BB * EE];       // gathered embeddings, 64 MB
__device__ __align__(16) float g_h[2][BB * HH];          // double-buffered hidden state
__device__ unsigned g_count;                             // barrier arrive counter (zero-init)
__device__ volatile unsigned g_gen;                      // barrier generation

// ---------------- prep: pack weights (i,g,o blocks, transposed, fused bias) --
__global__ void pack_kernel(const float* __restrict__ W_ih, const float* __restrict__ W_hh,
                            const float* __restrict__ b_ih, const float* __restrict__ b_hh) {
    const int gate_blk[3] = {0, 2, 3};   // PyTorch order i,f,g,o -> keep i,g,o
    int idx = blockIdx.x * blockDim.x + threadIdx.x;
    const int total = KTOT * 3 * NJ;
    if (idx < total) {
        int k = idx / (3 * NJ);
        int r = idx - k * 3 * NJ;
        int g = r / NJ;
        int j = r - g * NJ;
        int row = gate_blk[g] * HH + j;
        g_Wp[idx] = (k < EE) ? W_ih[row * EE + k] : W_hh[row * HH + (k - EE)];
    }
    if (idx < 3 * NJ) {
        int g = idx / NJ;
        int j = idx - g * NJ;
        int row = gate_blk[g] * HH + j;
        g_biasp[idx] = b_ih[row] + b_hh[row];
    }
}

// ---------------- prep: embedding gather  Xe[t][b][e] ------------------------
__global__ void gather_kernel(const int* __restrict__ inputs, const float* __restrict__ embed) {
    int gid = blockIdx.x * blockDim.x + threadIdx.x;   // one float4
    const int total4 = SS * BB * (EE / 4);
    if (gid >= total4) return;
    int t = gid / (BB * (EE / 4));
    int r = gid - t * (BB * (EE / 4));
    int b = r / (EE / 4);
    int q = r - b * (EE / 4);
    int tok = inputs[b * SS + t];
    reinterpret_cast<float4*>(g_Xe)[gid] =
        reinterpret_cast<const float4*>(embed)[(size_t)tok * (EE / 4) + q];
}

// ---------------- prep: zero h0 (must run every launch/replay) ---------------
__global__ void zero_h_kernel() {
    int i = blockIdx.x * blockDim.x + threadIdx.x;
    if (i < BB * HH) g_h[0][i] = 0.0f;
}

// ---------------- global barrier (sense-reversing, all CTAs resident) --------
__device__ __forceinline__ void grid_barrier() {
    __syncthreads();
    if (threadIdx.x == 0) {
        __threadfence();
        unsigned my = g_gen;                 // current generation (monotonic)
        unsigned t = atomicAdd(&g_count, 1u);
        if (t == NBLK - 1u) {
            atomicExch(&g_count, 0u);
            __threadfence();
            g_gen = my + 1u;                 // release
        } else {
            while (g_gen == my) { __nanosleep(64); }
        }
        __threadfence();
    }
    __syncthreads();
}

// ---------------- helpers: register-staged tile loads (SW pipeline) ----------
__device__ __forceinline__ void load_x_regs(float4& xr0, float4& xr1,
                                            const float* __restrict__ xe,
                                            const float* __restrict__ hprev,
                                            int k0, int m0, int ml, int kq) {
    const float* src; int stride, kk0;
    if (k0 < EE) { src = xe;    stride = EE; kk0 = k0; }
    else         { src = hprev; stride = HH; kk0 = k0 - EE; }
    const float* p = src + (size_t)(m0 + ml) * stride + kk0 + kq * 4;
    xr0 = *reinterpret_cast<const float4*>(p);
    xr1 = *reinterpret_cast<const float4*>(p + 16);
}

__device__ __forceinline__ void load_w_regs(float wr[6], int k0, int j0, int tid) {
#pragma unroll
    for (int u = 0; u < 6; ++u) {
        int i = tid + u * 256;               // 0..1535 over 32k x 48(=3*16)
        int kk = i / 48;
        int r  = i - kk * 48;                // g*16 + jj
        int g  = r >> 4;
        int jj = r & 15;
        wr[u] = g_Wp[(size_t)(k0 + kk) * (3 * NJ) + g * NJ + (j0 + jj)];
    }
}

// ---------------- persistent recurrent kernel --------------------------------
__global__ void __launch_bounds__(256, 1) lstm_kernel(float* __restrict__ out) {
    __shared__ __align__(16) float Xs[BK][BM + 4];   // stride 68 floats (16B aligned rows)
    __shared__ float Ws[BK][3 * BJ];

    const int tid = threadIdx.x;
    const int tx  = tid & 15;        // j within tile
    const int ty  = tid >> 4;        // m-group (4 rows each)
    const int j0  = blockIdx.x * BJ;
    const int m0  = blockIdx.y * BM;
    const int ml  = tid >> 2;        // loader: row 0..63
    const int kq  = tid & 3;         // loader: k quad

    const float bi = g_biasp[0 * NJ + j0 + tx];
    const float bg = g_biasp[1 * NJ + j0 + tx];
    const float bo = g_biasp[2 * NJ + j0 + tx];

    for (int t = 0; t < SS; ++t) {
        const float* __restrict__ hprev = g_h[t & 1];
        float* __restrict__ hnext = g_h[(t + 1) & 1];
        const float* __restrict__ xe = g_Xe + (size_t)t * BB * EE;

        float acc[3][4];
#pragma unroll
        for (int g = 0; g < 3; ++g)
#pragma unroll
            for (int m = 0; m < 4; ++m) acc[g][m] = 0.0f;

        // preload tile 0 (k0=0 < E: reads Xe only)
        float4 xr0, xr1;
        float wr[6];
        load_x_regs(xr0, xr1, xe, hprev, 0, m0, ml, kq);
        load_w_regs(wr, 0, j0, tid);

        for (int kt = 0; kt < KTOT / BK; ++kt) {
            __syncthreads();   // previous compute done reading smem
            // stage registers -> smem
            {
                int kb = kq * 4;
                Xs[kb + 0][ml] = xr0.x;  Xs[kb + 1][ml] = xr0.y;
                Xs[kb + 2][ml] = xr0.z;  Xs[kb + 3][ml] = xr0.w;
                Xs[kb + 16][ml] = xr1.x; Xs[kb + 17][ml] = xr1.y;
                Xs[kb + 18][ml] = xr1.z; Xs[kb + 19][ml] = xr1.w;
#pragma unroll
                for (int u = 0; u < 6; ++u) {
                    int i = tid + u * 256;
                    int kk = i / 48;
                    int r  = i - kk * 48;
                    Ws[kk][r] = wr[u];
                }
            }
            __syncthreads();
            // prefetch next tile into registers (hide L2 latency under compute)
            if (kt + 1 < KTOT / BK) {
                int k0n = (kt + 1) * BK;
                load_x_regs(xr0, xr1, xe, hprev, k0n, m0, ml, kq);
                load_w_regs(wr, k0n, j0, tid);
            }
            // compute
#pragma unroll
            for (int kk = 0; kk < BK; ++kk) {
                float4 xv = *reinterpret_cast<const float4*>(&Xs[kk][ty * 4]);
                float wi = Ws[kk][tx];
                float wg = Ws[kk][16 + tx];
                float wo = Ws[kk][32 + tx];
                acc[0][0] += xv.x * wi; acc[0][1] += xv.y * wi;
                acc[0][2] += xv.z * wi; acc[0][3] += xv.w * wi;
                acc[1][0] += xv.x * wg; acc[1][1] += xv.y * wg;
                acc[1][2] += xv.z * wg; acc[1][3] += xv.w * wg;
                acc[2][0] += xv.x * wo; acc[2][1] += xv.y * wo;
                acc[2][2] += xv.z * wo; acc[2][3] += xv.w * wo;
            }
        }

        // epilogue: h = sigmoid(o) * tanh( sigmoid(i) * tanh(g) )   (cell carry is zero)
#pragma unroll
        for (int m = 0; m < 4; ++m) {
            int row = m0 + ty * 4 + m;
            float iv = acc[0][m] + bi;
            float gv = acc[1][m] + bg;
            float ov = acc[2][m] + bo;
            float ct = (1.0f / (1.0f + expf(-iv))) * tanhf(gv);
            float hv = (1.0f / (1.0f + expf(-ov))) * tanhf(ct);
            hnext[(size_t)row * HH + j0 + tx] = hv;
            if (t == SS - 1) out[(size_t)row * HH + j0 + tx] = hv;
        }

        grid_barrier();
    }
}

// ---------------- launch -----------------------------------------------------
extern "C" void kernel_launch(void* const* d_in, const int* in_sizes, int n_in,
                              void* d_out, int out_size) {
    const int*   inputs = (const int*)  d_in[0];
    const float* embed  = (const float*)d_in[1];
    const float* W_ih   = (const float*)d_in[2];
    const float* W_hh   = (const float*)d_in[3];
    const float* b_ih   = (const float*)d_in[4];
    const float* b_hh   = (const float*)d_in[5];
    float* out = (float*)d_out;

    const int totalW = KTOT * 3 * NJ;
    pack_kernel<<<(totalW + 255) / 256, 256>>>(W_ih, W_hh, b_ih, b_hh);

    const int total4 = SS * BB * (EE / 4);
    gather_kernel<<<(total4 + 255) / 256, 256>>>(inputs, embed);

    zero_h_kernel<<<(BB * HH + 255) / 256, 256>>>();

    dim3 grid(NJ / BJ, BB / BM);   // (64, 2) = 128 CTAs, all co-resident on 148 SMs
    lstm_kernel<<<grid, 256>>>(out);
}

// round 4
// speedup vs baseline: 1.5116x; 1.4621x over previous
#include <cuda_runtime.h>
#include <cuda_bf16.h>
#include <math.h>

#define BB 128
#define SS 256
#define EE 512
#define HH 1024

// ---------- recurrent kernel geometry ----------
#define RC_NCTA 64
#define RC_JT   16          // j columns per CTA
#define RC_N    48          // 3 gates * 16
#define WS_STRIDE 2064      // 1024 bf16 (2048B) + 16B pad -> ldmatrix conflict-free
#define WHI_OFF 0
#define WLO_OFF 99072       // 48*2064
#define ABASE   198144      // 2*99072
#define ASLOT   12288       // per slot: hi 128*48 + lo 128*48
#define ALO     6144
#define RC_DSMEM 222720     // 198144 + 2*12288

// ---------- precompute kernel geometry ----------
#define PC_JB 16
#define PC_JT 64
#define PC_N  192           // 3 gates * 64
#define PC_WH 0
#define PC_WL 9216          // 192*48
#define PC_AH 18432
#define PC_AL 24576
#define PC_SLOT 30720
#define PC_DSMEM 61440

// ---------- globals (no allocations allowed) ----------
__device__ __align__(16) float g_Xe[(size_t)SS * BB * EE];                 // 64 MB
__device__ __align__(16) float g_xpart[(size_t)SS * BB * 3 * HH];          // 402 MB [t][m][ng]
__device__ float g_biasp[3 * HH];
__device__ __align__(16) __nv_bfloat16 g_h_hi[2][BB * HH];
__device__ __align__(16) __nv_bfloat16 g_h_lo[2][BB * HH];
__device__ unsigned g_count;
__device__ volatile unsigned g_gen;

__constant__ int c_blk[3] = {0, 2, 3};   // PyTorch gate order i,f,g,o -> keep i,g,o

// ---------- helpers ----------
__device__ __forceinline__ unsigned smem_u32(const void* p) {
    unsigned a;
    asm("{ .reg .u64 t; cvta.to.shared.u64 t, %1; cvt.u32.u64 %0, t; }" : "=r"(a) : "l"(p));
    return a;
}
__device__ __forceinline__ void ldsm4(unsigned r[4], unsigned addr) {
    asm volatile("ldmatrix.sync.aligned.m8n8.x4.shared.b16 {%0,%1,%2,%3}, [%4];"
        : "=r"(r[0]), "=r"(r[1]), "=r"(r[2]), "=r"(r[3]) : "r"(addr));
}
__device__ __forceinline__ void ldsm2(unsigned r[2], unsigned addr) {
    asm volatile("ldmatrix.sync.aligned.m8n8.x2.shared.b16 {%0,%1}, [%2];"
        : "=r"(r[0]), "=r"(r[1]) : "r"(addr));
}
__device__ __forceinline__ void mma_bf16(float d[4], const unsigned a[4], unsigned b0, unsigned b1) {
    asm volatile("mma.sync.aligned.m16n8k16.row.col.f32.bf16.bf16.f32 "
        "{%0,%1,%2,%3}, {%4,%5,%6,%7}, {%8,%9}, {%0,%1,%2,%3};"
        : "+f"(d[0]), "+f"(d[1]), "+f"(d[2]), "+f"(d[3])
        : "r"(a[0]), "r"(a[1]), "r"(a[2]), "r"(a[3]), "r"(b0), "r"(b1));
}
__device__ __forceinline__ unsigned packbf2(__nv_bfloat16 a, __nv_bfloat16 b) {
    return ((unsigned)__bfloat16_as_ushort(b) << 16) | (unsigned)__bfloat16_as_ushort(a);
}
// split pair of floats into bf16 hi word + lo word
__device__ __forceinline__ void split2(float a, float b, unsigned& hw, unsigned& lw) {
    __nv_bfloat16 ha = __float2bfloat16(a), hb = __float2bfloat16(b);
    __nv_bfloat16 la = __float2bfloat16(a - __bfloat162float(ha));
    __nv_bfloat16 lb = __float2bfloat16(b - __bfloat162float(hb));
    hw = packbf2(ha, hb);
    lw = packbf2(la, lb);
}
// split 16 floats -> 2x uint4 hi + 2x uint4 lo, store to smem
__device__ __forceinline__ void split_sts16(char* hi_dst, char* lo_dst, const float4 f[4]) {
    unsigned hw[8], lw[8];
#pragma unroll
    for (int i = 0; i < 4; ++i) {
        split2(f[i].x, f[i].y, hw[2 * i], lw[2 * i]);
        split2(f[i].z, f[i].w, hw[2 * i + 1], lw[2 * i + 1]);
    }
    *(uint4*)hi_dst        = make_uint4(hw[0], hw[1], hw[2], hw[3]);
    *(uint4*)(hi_dst + 16) = make_uint4(hw[4], hw[5], hw[6], hw[7]);
    *(uint4*)lo_dst        = make_uint4(lw[0], lw[1], lw[2], lw[3]);
    *(uint4*)(lo_dst + 16) = make_uint4(lw[4], lw[5], lw[6], lw[7]);
}
__device__ __forceinline__ float sigm_f(float x) { return __fdividef(1.0f, 1.0f + __expf(-x)); }
__device__ __forceinline__ float tanh_f(float x) {
    return 1.0f - __fdividef(2.0f, __expf(2.0f * x) + 1.0f);
}

// ---------- prep kernels ----------
__global__ void gather_kernel(const int* __restrict__ inputs, const float* __restrict__ embed) {
    int gid = blockIdx.x * blockDim.x + threadIdx.x;
    const int total4 = SS * BB * (EE / 4);
    if (gid >= total4) return;
    int t = gid / (BB * (EE / 4));
    int r = gid - t * (BB * (EE / 4));
    int m = r / (EE / 4);
    int q = r - m * (EE / 4);
    int tok = inputs[m * SS + t];
    ((float4*)g_Xe)[gid] = ((const float4*)embed)[(size_t)tok * (EE / 4) + q];
}
__global__ void pack_bias(const float* __restrict__ b_ih, const float* __restrict__ b_hh) {
    int idx = blockIdx.x * blockDim.x + threadIdx.x;
    if (idx >= 3 * HH) return;
    int g = idx >> 10, j = idx & 1023;
    int row = c_blk[g] * HH + j;
    g_biasp[idx] = b_ih[row] + b_hh[row];
}
__global__ void zero_h() {
    int i = blockIdx.x * blockDim.x + threadIdx.x;
    if (i < BB * HH) {
        g_h_hi[0][i] = __ushort_as_bfloat16(0);
        g_h_lo[0][i] = __ushort_as_bfloat16(0);
    }
}

// ---------- precompute: g_xpart[t][m][ng] = x_t @ W_ih^T + bias (gates i,g,o) ----------
__global__ void __launch_bounds__(256, 1) precompute_kernel(const float* __restrict__ W_ih) {
    extern __shared__ __align__(16) char smem[];
    const unsigned sb = smem_u32(smem);
    const int tid = threadIdx.x;
    const int lane = tid & 31;
    const int wid = tid >> 5;
    const int wm = wid & 3, wn = wid >> 2;
    const int jb = blockIdx.x;
    const int t = blockIdx.y;
    const int grp = lane >> 3, r = lane & 7;

    // loader roles
    const bool isW = tid < PC_N;
    const bool isA = tid >= 128;
    const float* wptr = nullptr;
    if (isW) {
        int g = tid >> 6, jj = tid & 63;
        wptr = W_ih + (size_t)(c_blk[g] * HH + jb * PC_JT + jj) * EE;
    }
    const float* aptr = isA ? (g_Xe + ((size_t)t * BB + (tid - 128)) * EE) : nullptr;

    // ldmatrix lane offsets (chunk-invariant)
    unsigned aoffP[2], b4offP;
#pragma unroll
    for (int tt = 0; tt < 2; ++tt)
        aoffP[tt] = PC_AH + (unsigned)((wm * 32 + tt * 16 + (grp & 1) * 8 + r) * 48 + (grp >> 1) * 16);
    b4offP = PC_WH + (unsigned)((wn * 96 + (grp >> 1) * 8 + r) * 48 + (grp & 1) * 16);

    float acc[2][12][4];
#pragma unroll
    for (int a = 0; a < 2; ++a)
#pragma unroll
        for (int j = 0; j < 12; ++j)
#pragma unroll
            for (int q = 0; q < 4; ++q) acc[a][j][q] = 0.0f;

    float4 wreg[4], areg[4];
    // chunk 0 stage
    if (isW) { const float4* p = (const float4*)(wptr); wreg[0]=p[0]; wreg[1]=p[1]; wreg[2]=p[2]; wreg[3]=p[3]; }
    if (isA) { const float4* p = (const float4*)(aptr); areg[0]=p[0]; areg[1]=p[1]; areg[2]=p[2]; areg[3]=p[3]; }
    {
        char* slot0 = smem;
        if (isW) split_sts16(slot0 + PC_WH + tid * 48, slot0 + PC_WL + tid * 48, wreg);
        if (isA) split_sts16(slot0 + PC_AH + (tid - 128) * 48, slot0 + PC_AL + (tid - 128) * 48, areg);
    }
    __syncthreads();

    for (int c = 0; c < EE / 16; ++c) {
        if (c < EE / 16 - 1) {
            if (isW) { const float4* p = (const float4*)(wptr + (c + 1) * 16); wreg[0]=p[0]; wreg[1]=p[1]; wreg[2]=p[2]; wreg[3]=p[3]; }
            if (isA) { const float4* p = (const float4*)(aptr + (c + 1) * 16); areg[0]=p[0]; areg[1]=p[1]; areg[2]=p[2]; areg[3]=p[3]; }
        }
        unsigned sbase = sb + (unsigned)(c & 1) * PC_SLOT;
        unsigned Ah[2][4], Al[2][4];
#pragma unroll
        for (int tt = 0; tt < 2; ++tt) {
            ldsm4(Ah[tt], sbase + aoffP[tt]);
            ldsm4(Al[tt], sbase + aoffP[tt] + (PC_AL - PC_AH));
        }
#pragma unroll
        for (int p = 0; p < 6; ++p) {
            unsigned Bh[4], Bl[4];
            ldsm4(Bh, sbase + b4offP + (unsigned)p * 768);
            ldsm4(Bl, sbase + b4offP + (unsigned)p * 768 + PC_WL);
#pragma unroll
            for (int tt = 0; tt < 2; ++tt) {
#pragma unroll
                for (int jj = 0; jj < 2; ++jj) {
                    int j = p * 2 + jj;
                    mma_bf16(acc[tt][j], Ah[tt], Bh[2 * jj], Bh[2 * jj + 1]);
                    mma_bf16(acc[tt][j], Ah[tt], Bl[2 * jj], Bl[2 * jj + 1]);
                    mma_bf16(acc[tt][j], Al[tt], Bh[2 * jj], Bh[2 * jj + 1]);
                }
            }
        }
        if (c < EE / 16 - 1) {
            char* slot = smem + ((c + 1) & 1) * PC_SLOT;
            if (isW) split_sts16(slot + PC_WH + tid * 48, slot + PC_WL + tid * 48, wreg);
            if (isA) split_sts16(slot + PC_AH + (tid - 128) * 48, slot + PC_AL + (tid - 128) * 48, areg);
        }
        __syncthreads();
    }

    // epilogue: + bias -> g_xpart[t][m][ng]
    const int mrow = lane >> 2, nc = (lane & 3) * 2;
#pragma unroll
    for (int tt = 0; tt < 2; ++tt) {
#pragma unroll
        for (int j = 0; j < 12; ++j) {
            int np = wn * 96 + j * 8 + nc;
            int g = np >> 6, jj = np & 63;
            int ng = g * HH + jb * PC_JT + jj;
            float2 bv = *(const float2*)&g_biasp[ng];
            int m = wm * 32 + tt * 16 + mrow;
            float* o0 = g_xpart + ((size_t)t * BB + m) * (3 * HH) + ng;
            *(float2*)o0 = make_float2(acc[tt][j][0] + bv.x, acc[tt][j][1] + bv.y);
            *(float2*)(o0 + (size_t)8 * (3 * HH)) =
                make_float2(acc[tt][j][2] + bv.x, acc[tt][j][3] + bv.y);
        }
    }
}

// ---------- grid barrier ----------
__device__ __forceinline__ void grid_barrier() {
    __syncthreads();
    if (threadIdx.x == 0) {
        __threadfence();
        unsigned my = g_gen;
        unsigned t = atomicAdd(&g_count, 1u);
        if (t == RC_NCTA - 1u) {
            atomicExch(&g_count, 0u);
            __threadfence();
            g_gen = my + 1u;
        } else {
            while (g_gen == my) { __nanosleep(32); }
        }
        __threadfence();
    }
    __syncthreads();
}

// ---------- persistent recurrent kernel ----------
__global__ void __launch_bounds__(256, 1) lstm_rec_kernel(const float* __restrict__ W_hh,
                                                          float* __restrict__ out) {
    extern __shared__ __align__(16) char smem[];
    const unsigned sb = smem_u32(smem);
    const int tid = threadIdx.x;
    const int lane = tid & 31;
    const int wid = tid >> 5;
    const int wm = wid & 3, wn = wid >> 2;
    const int cta = blockIdx.x;
    const int j0 = cta * RC_JT;
    const int grp = lane >> 3, r = lane & 7;

    // prologue: load + split W_hh rows for this CTA's 48 n-columns into resident SMEM
    {
        const float4* Wv = (const float4*)W_hh;
        for (int i = tid; i < RC_N * (HH / 4); i += 256) {
            int n = i >> 8;            // 256 float4 per row
            int kq = i & 255;
            int g = n >> 4, jj = n & 15;
            int rowg = c_blk[g] * HH + cta * RC_JT + jj;
            float4 v = Wv[(size_t)rowg * (HH / 4) + kq];
            unsigned hw0, lw0, hw1, lw1;
            split2(v.x, v.y, hw0, lw0);
            split2(v.z, v.w, hw1, lw1);
            char* dh = smem + WHI_OFF + n * WS_STRIDE + kq * 8;
            char* dl = smem + WLO_OFF + n * WS_STRIDE + kq * 8;
            *(uint2*)dh = make_uint2(hw0, hw1);
            *(uint2*)dl = make_uint2(lw0, lw1);
        }
    }

    // ldmatrix lane offsets (invariant)
    unsigned aoff[2];
#pragma unroll
    for (int tt = 0; tt < 2; ++tt)
        aoff[tt] = (unsigned)((wm * 32 + tt * 16 + (grp & 1) * 8 + r) * 48 + (grp >> 1) * 16);
    const unsigned b4off = (unsigned)((wn * 24 + (grp >> 1) * 8 + r) * WS_STRIDE + (grp & 1) * 16);
    const int l2 = lane & 15;
    const unsigned b2off = (unsigned)((wn * 24 + 16 + (l2 & 7)) * WS_STRIDE + (l2 >> 3) * 16);

    const int lrow = tid >> 1;       // h loader: row
    const int lhalf = tid & 1;       // 16B half of the 32B hi/lo row slice
    float* Gs = (float*)(smem + ABASE);

    __syncthreads();   // W resident

    for (int t = 0; t < SS; ++t) {
        const __nv_bfloat16* __restrict__ hh = g_h_hi[t & 1];
        const __nv_bfloat16* __restrict__ hl = g_h_lo[t & 1];

        float acc[2][3][4];
#pragma unroll
        for (int a = 0; a < 2; ++a)
#pragma unroll
            for (int j = 0; j < 3; ++j)
#pragma unroll
                for (int q = 0; q < 4; ++q) acc[a][j][q] = 0.0f;

        // stage chunk 0 (cg loads: h written by other SMs last step; L1 is stale)
        uint4 rhi = __ldcg((const uint4*)(hh + (size_t)lrow * HH + lhalf * 8));
        uint4 rlo = __ldcg((const uint4*)(hl + (size_t)lrow * HH + lhalf * 8));
        *(uint4*)(smem + ABASE + lrow * 48 + lhalf * 16)       = rhi;
        *(uint4*)(smem + ABASE + ALO + lrow * 48 + lhalf * 16) = rlo;
        __syncthreads();

        for (int c = 0; c < HH / 16; ++c) {
            if (c < HH / 16 - 1) {
                rhi = __ldcg((const uint4*)(hh + (size_t)lrow * HH + (c + 1) * 16 + lhalf * 8));
                rlo = __ldcg((const uint4*)(hl + (size_t)lrow * HH + (c + 1) * 16 + lhalf * 8));
            }
            // compute from slot c&1
            unsigned ab = sb + ABASE + (unsigned)(c & 1) * ASLOT;
            unsigned Ah[2][4], Al[2][4];
#pragma unroll
            for (int tt = 0; tt < 2; ++tt) {
                ldsm4(Ah[tt], ab + aoff[tt]);
                ldsm4(Al[tt], ab + aoff[tt] + ALO);
            }
            unsigned wb = sb + WHI_OFF + (unsigned)c * 32;
            unsigned B01h[4], B01l[4], B2h[2], B2l[2];
            ldsm4(B01h, wb + b4off);
            ldsm4(B01l, wb + b4off + WLO_OFF);
            ldsm2(B2h, wb + b2off);
            ldsm2(B2l, wb + b2off + WLO_OFF);
#pragma unroll
            for (int tt = 0; tt < 2; ++tt) {
                mma_bf16(acc[tt][0], Ah[tt], B01h[0], B01h[1]);
                mma_bf16(acc[tt][0], Ah[tt], B01l[0], B01l[1]);
                mma_bf16(acc[tt][0], Al[tt], B01h[0], B01h[1]);
                mma_bf16(acc[tt][1], Ah[tt], B01h[2], B01h[3]);
                mma_bf16(acc[tt][1], Ah[tt], B01l[2], B01l[3]);
                mma_bf16(acc[tt][1], Al[tt], B01h[2], B01h[3]);
                mma_bf16(acc[tt][2], Ah[tt], B2h[0], B2h[1]);
                mma_bf16(acc[tt][2], Ah[tt], B2l[0], B2l[1]);
                mma_bf16(acc[tt][2], Al[tt], B2h[0], B2h[1]);
            }
            if (c < HH / 16 - 1) {
                char* slot = smem + ABASE + ((c + 1) & 1) * ASLOT;
                *(uint4*)(slot + lrow * 48 + lhalf * 16)       = rhi;
                *(uint4*)(slot + ALO + lrow * 48 + lhalf * 16) = rlo;
            }
            __syncthreads();
        }

        // exchange gates through SMEM (reuses A slots; all MMA reads done)
        {
            const int mrow = lane >> 2, nc = (lane & 3) * 2;
#pragma unroll
            for (int tt = 0; tt < 2; ++tt) {
#pragma unroll
                for (int j = 0; j < 3; ++j) {
                    int m = wm * 32 + tt * 16 + mrow;
                    int n = wn * 24 + j * 8 + nc;
                    *(float2*)&Gs[m * 48 + n] = make_float2(acc[tt][j][0], acc[tt][j][1]);
                    *(float2*)&Gs[(m + 8) * 48 + n] = make_float2(acc[tt][j][2], acc[tt][j][3]);
                }
            }
        }
        __syncthreads();

        // epilogue: h = sigmoid(o) * tanh( sigmoid(i) * tanh(g) )
        {
            const int m = tid >> 1;
            const int jj0 = (tid & 1) * 8;
            const float* xpm = g_xpart + ((size_t)t * BB + m) * (3 * HH) + j0;
            const float* gsm = Gs + m * 48;
            float hv[8];
#pragma unroll
            for (int q = 0; q < 8; ++q) {
                int jj = jj0 + q;
                float iv = gsm[jj]      + xpm[jj];
                float gv = gsm[16 + jj] + xpm[HH + jj];
                float ov = gsm[32 + jj] + xpm[2 * HH + jj];
                float ct = sigm_f(iv) * tanh_f(gv);
                hv[q] = sigm_f(ov) * tanh_f(ct);
            }
            unsigned hw[4], lw[4];
#pragma unroll
            for (int q = 0; q < 4; ++q) split2(hv[2 * q], hv[2 * q + 1], hw[q], lw[q]);
            *(uint4*)(g_h_hi[(t + 1) & 1] + (size_t)m * HH + j0 + jj0) =
                make_uint4(hw[0], hw[1], hw[2], hw[3]);
            *(uint4*)(g_h_lo[(t + 1) & 1] + (size_t)m * HH + j0 + jj0) =
                make_uint4(lw[0], lw[1], lw[2], lw[3]);
            if (t == SS - 1) {
                float4* po = (float4*)(out + (size_t)m * HH + j0 + jj0);
                po[0] = make_float4(hv[0], hv[1], hv[2], hv[3]);
                po[1] = make_float4(hv[4], hv[5], hv[6], hv[7]);
            }
        }

        grid_barrier();
    }
}

// ---------- launch ----------
extern "C" void kernel_launch(void* const* d_in, const int* in_sizes, int n_in,
                              void* d_out, int out_size) {
    const int*   inputs = (const int*)  d_in[0];
    const float* embed  = (const float*)d_in[1];
    const float* W_ih   = (const float*)d_in[2];
    const float* W_hh   = (const float*)d_in[3];
    const float* b_ih   = (const float*)d_in[4];
    const float* b_hh   = (const float*)d_in[5];
    float* out = (float*)d_out;

    static int attr_done = 0;
    if (!attr_done) {
        cudaFuncSetAttribute(precompute_kernel, cudaFuncAttributeMaxDynamicSharedMemorySize, PC_DSMEM);
        cudaFuncSetAttribute(lstm_rec_kernel,  cudaFuncAttributeMaxDynamicSharedMemorySize, RC_DSMEM);
        attr_done = 1;
    }

    const int total4 = SS * BB * (EE / 4);
    gather_kernel<<<(total4 + 255) / 256, 256>>>(inputs, embed);
    pack_bias<<<(3 * HH + 255) / 256, 256>>>(b_ih, b_hh);
    zero_h<<<(BB * HH + 255) / 256, 256>>>();

    dim3 pgrid(PC_JB, SS);
    precompute_kernel<<<pgrid, 256, PC_DSMEM>>>(W_ih);

    lstm_rec_kernel<<<RC_NCTA, 256, RC_DSMEM>>>(W_hh, out);
}

// round 6
// speedup vs baseline: 3.2830x; 2.1718x over previous
#include <cuda_runtime.h>
#include <cuda_bf16.h>
#include <cuda_fp16.h>
#include <math.h>

#define BB 128
#define SS 256
#define EE 512
#define HH 1024

// ---------- recurrent geometry: 128 CTAs x 256 thr (8 warps), N=24, K=1024, fp16 ----------
#define RC_NCTA 128
#define RC_JT   8            // j columns per CTA
#define WS_STRIDE 2064       // 1024 fp16 (2048B) + 16B pad: ldmatrix conflict-free
#define AW_BASE 49536        // 24 * 2064
#define AW_WARP 1536         // per-warp A region: 2 slots x (16 rows x 48B)
#define GS_OFF  61824        // 49536 + 8*1536
#define GS_STRIDE 25         // floats, conflict-free column reads
#define RC_DSMEM 74624       // 61824 + 128*25*4

// ---------- precompute geometry (validated round 4) ----------
#define PC_JB 16
#define PC_JT 64
#define PC_N  192
#define PC_WH 0
#define PC_WL 9216
#define PC_AH 18432
#define PC_AL 24576
#define PC_SLOT 30720
#define PC_DSMEM 61440

// ---------- globals ----------
__device__ __align__(16) float g_Xe[(size_t)SS * BB * EE];
__device__ __align__(16) float g_xpart[(size_t)SS * BB * 3 * HH];   // [t][m][ng]
__device__ float g_biasp[3 * HH];
__device__ __align__(16) __half g_h[2][BB * HH];                    // fp16 hidden state
__device__ unsigned g_count;
__device__ volatile unsigned g_gen;

__constant__ int c_blk[3] = {0, 2, 3};   // PyTorch i,f,g,o -> keep i,g,o (f is dead)

// ---------- helpers ----------
__device__ __forceinline__ unsigned smem_u32(const void* p) {
    unsigned a;
    asm("{ .reg .u64 t; cvta.to.shared.u64 t, %1; cvt.u32.u64 %0, t; }" : "=r"(a) : "l"(p));
    return a;
}
__device__ __forceinline__ void ldsm4(unsigned r[4], unsigned addr) {
    asm volatile("ldmatrix.sync.aligned.m8n8.x4.shared.b16 {%0,%1,%2,%3}, [%4];"
        : "=r"(r[0]), "=r"(r[1]), "=r"(r[2]), "=r"(r[3]) : "r"(addr));
}
__device__ __forceinline__ void ldsm2(unsigned r[2], unsigned addr) {
    asm volatile("ldmatrix.sync.aligned.m8n8.x2.shared.b16 {%0,%1}, [%2];"
        : "=r"(r[0]), "=r"(r[1]) : "r"(addr));
}
__device__ __forceinline__ void mma_bf16(float d[4], const unsigned a[4], unsigned b0, unsigned b1) {
    asm volatile("mma.sync.aligned.m16n8k16.row.col.f32.bf16.bf16.f32 "
        "{%0,%1,%2,%3}, {%4,%5,%6,%7}, {%8,%9}, {%0,%1,%2,%3};"
        : "+f"(d[0]), "+f"(d[1]), "+f"(d[2]), "+f"(d[3])
        : "r"(a[0]), "r"(a[1]), "r"(a[2]), "r"(a[3]), "r"(b0), "r"(b1));
}
__device__ __forceinline__ void mma_f16(float d[4], const unsigned a[4], unsigned b0, unsigned b1) {
    asm volatile("mma.sync.aligned.m16n8k16.row.col.f32.f16.f16.f32 "
        "{%0,%1,%2,%3}, {%4,%5,%6,%7}, {%8,%9}, {%0,%1,%2,%3};"
        : "+f"(d[0]), "+f"(d[1]), "+f"(d[2]), "+f"(d[3])
        : "r"(a[0]), "r"(a[1]), "r"(a[2]), "r"(a[3]), "r"(b0), "r"(b1));
}
__device__ __forceinline__ unsigned packbf2(__nv_bfloat16 a, __nv_bfloat16 b) {
    return ((unsigned)__bfloat16_as_ushort(b) << 16) | (unsigned)__bfloat16_as_ushort(a);
}
__device__ __forceinline__ void split2(float a, float b, unsigned& hw, unsigned& lw) {
    __nv_bfloat16 ha = __float2bfloat16(a), hb = __float2bfloat16(b);
    __nv_bfloat16 la = __float2bfloat16(a - __bfloat162float(ha));
    __nv_bfloat16 lb = __float2bfloat16(b - __bfloat162float(hb));
    hw = packbf2(ha, hb);
    lw = packbf2(la, lb);
}
__device__ __forceinline__ void split_sts16(char* hi_dst, char* lo_dst, const float4 f[4]) {
    unsigned hw[8], lw[8];
#pragma unroll
    for (int i = 0; i < 4; ++i) {
        split2(f[i].x, f[i].y, hw[2 * i], lw[2 * i]);
        split2(f[i].z, f[i].w, hw[2 * i + 1], lw[2 * i + 1]);
    }
    *(uint4*)hi_dst        = make_uint4(hw[0], hw[1], hw[2], hw[3]);
    *(uint4*)(hi_dst + 16) = make_uint4(hw[4], hw[5], hw[6], hw[7]);
    *(uint4*)lo_dst        = make_uint4(lw[0], lw[1], lw[2], lw[3]);
    *(uint4*)(lo_dst + 16) = make_uint4(lw[4], lw[5], lw[6], lw[7]);
}
__device__ __forceinline__ unsigned h2_bits(__half2 v) {
    return *reinterpret_cast<unsigned*>(&v);
}
__device__ __forceinline__ float sigm_f(float x) { return __fdividef(1.0f, 1.0f + __expf(-x)); }
__device__ __forceinline__ float tanh_f(float x) {
    return 1.0f - __fdividef(2.0f, __expf(2.0f * x) + 1.0f);
}

// ---------- prep kernels ----------
__global__ void gather_kernel(const int* __restrict__ inputs, const float* __restrict__ embed) {
    int gid = blockIdx.x * blockDim.x + threadIdx.x;
    const int total4 = SS * BB * (EE / 4);
    if (gid >= total4) return;
    int t = gid / (BB * (EE / 4));
    int r = gid - t * (BB * (EE / 4));
    int m = r / (EE / 4);
    int q = r - m * (EE / 4);
    int tok = inputs[m * SS + t];
    ((float4*)g_Xe)[gid] = ((const float4*)embed)[(size_t)tok * (EE / 4) + q];
}
__global__ void pack_bias(const float* __restrict__ b_ih, const float* __restrict__ b_hh) {
    int idx = blockIdx.x * blockDim.x + threadIdx.x;
    if (idx >= 3 * HH) return;
    int g = idx >> 10, j = idx & 1023;
    int row = c_blk[g] * HH + j;
    g_biasp[idx] = b_ih[row] + b_hh[row];
}
__global__ void zero_h() {
    int i = blockIdx.x * blockDim.x + threadIdx.x;
    if (i < BB * HH) g_h[0][i] = __ushort_as_half((unsigned short)0);
}

// ---------- precompute: g_xpart[t][m][ng] = x_t @ W_ih^T + bias (bf16 3-pass) ----------
__global__ void __launch_bounds__(256, 1) precompute_kernel(const float* __restrict__ W_ih) {
    extern __shared__ __align__(16) char smem[];
    const unsigned sb = smem_u32(smem);
    const int tid = threadIdx.x;
    const int lane = tid & 31;
    const int wid = tid >> 5;
    const int wm = wid & 3, wn = wid >> 2;
    const int jb = blockIdx.x;
    const int t = blockIdx.y;
    const int grp = lane >> 3, r = lane & 7;

    const bool isW = tid < PC_N;
    const bool isA = tid >= 128;
    const float* wptr = nullptr;
    if (isW) {
        int g = tid >> 6, jj = tid & 63;
        wptr = W_ih + (size_t)(c_blk[g] * HH + jb * PC_JT + jj) * EE;
    }
    const float* aptr = isA ? (g_Xe + ((size_t)t * BB + (tid - 128)) * EE) : nullptr;

    unsigned aoffP[2], b4offP;
#pragma unroll
    for (int tt = 0; tt < 2; ++tt)
        aoffP[tt] = PC_AH + (unsigned)((wm * 32 + tt * 16 + (grp & 1) * 8 + r) * 48 + (grp >> 1) * 16);
    b4offP = PC_WH + (unsigned)((wn * 96 + (grp >> 1) * 8 + r) * 48 + (grp & 1) * 16);

    float acc[2][12][4];
#pragma unroll
    for (int a = 0; a < 2; ++a)
#pragma unroll
        for (int j = 0; j < 12; ++j)
#pragma unroll
            for (int q = 0; q < 4; ++q) acc[a][j][q] = 0.0f;

    float4 wreg[4], areg[4];
    if (isW) { const float4* p = (const float4*)(wptr); wreg[0]=p[0]; wreg[1]=p[1]; wreg[2]=p[2]; wreg[3]=p[3]; }
    if (isA) { const float4* p = (const float4*)(aptr); areg[0]=p[0]; areg[1]=p[1]; areg[2]=p[2]; areg[3]=p[3]; }
    {
        char* slot0 = smem;
        if (isW) split_sts16(slot0 + PC_WH + tid * 48, slot0 + PC_WL + tid * 48, wreg);
        if (isA) split_sts16(slot0 + PC_AH + (tid - 128) * 48, slot0 + PC_AL + (tid - 128) * 48, areg);
    }
    __syncthreads();

    for (int c = 0; c < EE / 16; ++c) {
        if (c < EE / 16 - 1) {
            if (isW) { const float4* p = (const float4*)(wptr + (c + 1) * 16); wreg[0]=p[0]; wreg[1]=p[1]; wreg[2]=p[2]; wreg[3]=p[3]; }
            if (isA) { const float4* p = (const float4*)(aptr + (c + 1) * 16); areg[0]=p[0]; areg[1]=p[1]; areg[2]=p[2]; areg[3]=p[3]; }
        }
        unsigned sbase = sb + (unsigned)(c & 1) * PC_SLOT;
        unsigned Ah[2][4], Al[2][4];
#pragma unroll
        for (int tt = 0; tt < 2; ++tt) {
            ldsm4(Ah[tt], sbase + aoffP[tt]);
            ldsm4(Al[tt], sbase + aoffP[tt] + (PC_AL - PC_AH));
        }
#pragma unroll
        for (int p = 0; p < 6; ++p) {
            unsigned Bh[4], Bl[4];
            ldsm4(Bh, sbase + b4offP + (unsigned)p * 768);
            ldsm4(Bl, sbase + b4offP + (unsigned)p * 768 + PC_WL);
#pragma unroll
            for (int tt = 0; tt < 2; ++tt) {
#pragma unroll
                for (int jj = 0; jj < 2; ++jj) {
                    int j = p * 2 + jj;
                    mma_bf16(acc[tt][j], Ah[tt], Bh[2 * jj], Bh[2 * jj + 1]);
                    mma_bf16(acc[tt][j], Ah[tt], Bl[2 * jj], Bl[2 * jj + 1]);
                    mma_bf16(acc[tt][j], Al[tt], Bh[2 * jj], Bh[2 * jj + 1]);
                }
            }
        }
        if (c < EE / 16 - 1) {
            char* slot = smem + ((c + 1) & 1) * PC_SLOT;
            if (isW) split_sts16(slot + PC_WH + tid * 48, slot + PC_WL + tid * 48, wreg);
            if (isA) split_sts16(slot + PC_AH + (tid - 128) * 48, slot + PC_AL + (tid - 128) * 48, areg);
        }
        __syncthreads();
    }

    const int mrow = lane >> 2, nc = (lane & 3) * 2;
#pragma unroll
    for (int tt = 0; tt < 2; ++tt) {
#pragma unroll
        for (int j = 0; j < 12; ++j) {
            int np = wn * 96 + j * 8 + nc;
            int g = np >> 6, jj = np & 63;
            int ng = g * HH + jb * PC_JT + jj;
            float2 bv = *(const float2*)&g_biasp[ng];
            int m = wm * 32 + tt * 16 + mrow;
            float* o0 = g_xpart + ((size_t)t * BB + m) * (3 * HH) + ng;
            *(float2*)o0 = make_float2(acc[tt][j][0] + bv.x, acc[tt][j][1] + bv.y);
            *(float2*)(o0 + (size_t)8 * (3 * HH)) =
                make_float2(acc[tt][j][2] + bv.x, acc[tt][j][3] + bv.y);
        }
    }
}

// ---------- grid barrier (128 CTAs) ----------
__device__ __forceinline__ void grid_barrier() {
    __syncthreads();
    if (threadIdx.x == 0) {
        __threadfence();
        unsigned my = g_gen;
        unsigned t = atomicAdd(&g_count, 1u);
        if (t == RC_NCTA - 1u) {
            atomicExch(&g_count, 0u);
            __threadfence();
            g_gen = my + 1u;
        } else {
            while (g_gen == my) { __nanosleep(32); }
        }
        __threadfence();
    }
    __syncthreads();
}

// ---------- persistent recurrent kernel: fp16 single-pass, warp-private A staging ----------
__global__ void __launch_bounds__(256, 1) lstm_rec_kernel(const float* __restrict__ W_hh,
                                                          float* __restrict__ out) {
    extern __shared__ __align__(16) char smem[];
    const unsigned sb = smem_u32(smem);
    const int tid = threadIdx.x;
    const int lane = tid & 31;
    const int w = tid >> 5;            // warp 0..7, owns m rows w*16..w*16+15
    const int cta = blockIdx.x;
    const int j0 = cta * RC_JT;
    const int grp = lane >> 3, r = lane & 7;

    // ---- prologue: W_hh fp16 resident in SMEM (24 n-rows x 1024 k) ----
    {
        const float4* Wv = (const float4*)W_hh;
        for (int i = tid; i < 24 * 256; i += 256) {
            int n = i >> 8;            // 0..23 = g*8+jj
            int kq = i & 255;
            int g = n >> 3, jj = n & 7;
            int rowg = c_blk[g] * HH + cta * RC_JT + jj;
            float4 v = Wv[(size_t)rowg * (HH / 4) + kq];
            __half2 h0 = __floats2half2_rn(v.x, v.y);
            __half2 h1 = __floats2half2_rn(v.z, v.w);
            char* d = smem + n * WS_STRIDE + kq * 8;
            *(__half2*)d = h0;
            *(__half2*)(d + 4) = h1;
        }
    }

    // ldmatrix lane offsets (invariant)
    const unsigned aoffb = (unsigned)(((grp & 1) * 8 + r) * 48 + (grp >> 1) * 16);
    const unsigned b4off = (unsigned)(((grp >> 1) * 8 + r) * WS_STRIDE + (grp & 1) * 16);
    const int l2 = lane & 15;
    const unsigned b2off = (unsigned)((16 + (l2 & 7)) * WS_STRIDE + (l2 >> 3) * 16);
    const unsigned AW = AW_BASE + (unsigned)w * AW_WARP;
    const unsigned sts_off = (unsigned)((lane >> 1) * 48 + (lane & 1) * 16);

    // epilogue mapping
    const int em = tid >> 1;
    const int ej = (tid & 1) * 4;
    float* Gs = (float*)(smem + GS_OFF);

    __syncthreads();   // W resident for all warps

    for (int t = 0; t < SS; ++t) {
        const __half* __restrict__ hs = g_h[t & 1];

        // prefetch this thread's xpart slice into registers (consumed in epilogue)
        const float* xpm = g_xpart + ((size_t)t * BB + em) * (3 * HH) + j0 + ej;
        float4 xi = __ldcg((const float4*)(xpm));
        float4 xg = __ldcg((const float4*)(xpm + HH));
        float4 xo = __ldcg((const float4*)(xpm + 2 * HH));

        float acc[3][4];
#pragma unroll
        for (int j = 0; j < 3; ++j)
#pragma unroll
            for (int q = 0; q < 4; ++q) acc[j][q] = 0.0f;

        // A source: lane covers row w*16 + (lane>>1), 16B half (lane&1)
        const __half* abase = hs + (size_t)(w * 16 + (lane >> 1)) * HH + (lane & 1) * 8;

        // depth-4 register prefetch (LDG c+4, STS c+2: ~2 chunks of latency cover)
        uint4 R[4];
        R[0] = __ldcg((const uint4*)(abase));
        R[1] = __ldcg((const uint4*)(abase + 16));
        R[2] = __ldcg((const uint4*)(abase + 32));
        R[3] = __ldcg((const uint4*)(abase + 48));
        *(uint4*)(smem + AW + 0 * 768 + sts_off) = R[0];
        *(uint4*)(smem + AW + 1 * 768 + sts_off) = R[1];
        __syncwarp();

        for (int c = 0; c < HH / 16; ++c) {
            unsigned ab = sb + AW + (unsigned)(c & 1) * 768;
            unsigned Af[4], Bh[4], B2[2];
            ldsm4(Af, ab + aoffb);
            unsigned wb = sb + (unsigned)c * 32;
            ldsm4(Bh, wb + b4off);
            ldsm2(B2, wb + b2off);
            mma_f16(acc[0], Af, Bh[0], Bh[1]);
            mma_f16(acc[1], Af, Bh[2], Bh[3]);
            mma_f16(acc[2], Af, B2[0], B2[1]);
            if (c + 2 < HH / 16)
                *(uint4*)(smem + AW + (unsigned)(c & 1) * 768 + sts_off) = R[(c + 2) & 3];
            if (c + 4 < HH / 16)
                R[c & 3] = __ldcg((const uint4*)(abase + (c + 4) * 16));
            __syncwarp();
        }

        // exchange gates via SMEM
        {
            const int mrow = lane >> 2, nc = (lane & 3) * 2;
#pragma unroll
            for (int j = 0; j < 3; ++j) {
                int m0 = w * 16 + mrow;
                int n = j * 8 + nc;
                Gs[m0 * GS_STRIDE + n]           = acc[j][0];
                Gs[m0 * GS_STRIDE + n + 1]       = acc[j][1];
                Gs[(m0 + 8) * GS_STRIDE + n]     = acc[j][2];
                Gs[(m0 + 8) * GS_STRIDE + n + 1] = acc[j][3];
            }
        }
        __syncthreads();

        // epilogue: h = sigmoid(o) * tanh( sigmoid(i) * tanh(g) )  (cell carry is zero)
        {
            const float* gsm = Gs + em * GS_STRIDE + ej;
            float xiv[4] = {xi.x, xi.y, xi.z, xi.w};
            float xgv[4] = {xg.x, xg.y, xg.z, xg.w};
            float xov[4] = {xo.x, xo.y, xo.z, xo.w};
            float hv[4];
#pragma unroll
            for (int q = 0; q < 4; ++q) {
                float iv = gsm[q]      + xiv[q];
                float gv = gsm[8 + q]  + xgv[q];
                float ov = gsm[16 + q] + xov[q];
                float ct = sigm_f(iv) * tanh_f(gv);
                hv[q] = sigm_f(ov) * tanh_f(ct);
            }
            __half2 p0 = __floats2half2_rn(hv[0], hv[1]);
            __half2 p1 = __floats2half2_rn(hv[2], hv[3]);
            *(uint2*)(g_h[(t + 1) & 1] + (size_t)em * HH + j0 + ej) =
                make_uint2(h2_bits(p0), h2_bits(p1));
            if (t == SS - 1)
                *(float4*)(out + (size_t)em * HH + j0 + ej) =
                    make_float4(hv[0], hv[1], hv[2], hv[3]);
        }

        grid_barrier();
    }
}

// ---------- launch ----------
extern "C" void kernel_launch(void* const* d_in, const int* in_sizes, int n_in,
                              void* d_out, int out_size) {
    const int*   inputs = (const int*)  d_in[0];
    const float* embed  = (const float*)d_in[1];
    const float* W_ih   = (const float*)d_in[2];
    const float* W_hh   = (const float*)d_in[3];
    const float* b_ih   = (const float*)d_in[4];
    const float* b_hh   = (const float*)d_in[5];
    float* out = (float*)d_out;

    static int attr_done = 0;
    if (!attr_done) {
        cudaFuncSetAttribute(precompute_kernel, cudaFuncAttributeMaxDynamicSharedMemorySize, PC_DSMEM);
        cudaFuncSetAttribute(lstm_rec_kernel,  cudaFuncAttributeMaxDynamicSharedMemorySize, RC_DSMEM);
        attr_done = 1;
    }

    const int total4 = SS * BB * (EE / 4);
    gather_kernel<<<(total4 + 255) / 256, 256>>>(inputs, embed);
    pack_bias<<<(3 * HH + 255) / 256, 256>>>(b_ih, b_hh);
    zero_h<<<(BB * HH + 255) / 256, 256>>>();

    dim3 pgrid(PC_JB, SS);
    precompute_kernel<<<pgrid, 256, PC_DSMEM>>>(W_ih);

    lstm_rec_kernel<<<RC_NCTA, 256, RC_DSMEM>>>(W_hh, out);
}

// round 7
// speedup vs baseline: 3.9118x; 1.1915x over previous
#include <cuda_runtime.h>
#include <cuda_bf16.h>
#include <cuda_fp16.h>
#include <math.h>

#define BB 128
#define SS 256
#define EE 512
#define HH 1024

// ---------- recurrent geometry: 128 CTAs x 256 thr (8 warps), N=24, K=1024, fp16 ----------
#define RC_NCTA 128
#define RC_JT   8            // j columns per CTA
#define WS_STRIDE 2064       // 1024 fp16 (2048B) + 16B pad: ldmatrix conflict-free
#define AW_BASE 49536        // 24 * 2064
#define A_SLOT  1280         // 16 rows x 80B (stride 80 -> conflict-free ldsm)
#define A_DEPTH 8
#define AW_WARP 10240        // 8 slots x 1280
#define GS_OFF  131456       // 49536 + 8*10240
#define GS_STRIDE 25         // floats
#define RC_DSMEM 144256      // 131456 + 128*25*4

// ---------- precompute geometry (validated round 4) ----------
#define PC_JB 16
#define PC_JT 64
#define PC_N  192
#define PC_WH 0
#define PC_WL 9216
#define PC_AH 18432
#define PC_AL 24576
#define PC_SLOT 30720
#define PC_DSMEM 61440

// ---------- globals ----------
__device__ __align__(16) float g_Xe[(size_t)SS * BB * EE];
__device__ __align__(16) float g_xpart[(size_t)SS * BB * 3 * HH];   // [t][m][ng]
__device__ float g_biasp[3 * HH];
__device__ __align__(16) __half g_h[2][BB * HH];                    // fp16 hidden state
__device__ unsigned g_count;
__device__ volatile unsigned g_gen;

__constant__ int c_blk[3] = {0, 2, 3};   // PyTorch i,f,g,o -> keep i,g,o (f is dead)

// ---------- helpers ----------
__device__ __forceinline__ unsigned smem_u32(const void* p) {
    unsigned a;
    asm("{ .reg .u64 t; cvta.to.shared.u64 t, %1; cvt.u32.u64 %0, t; }" : "=r"(a) : "l"(p));
    return a;
}
__device__ __forceinline__ void cp16(unsigned dst, const void* src) {
    asm volatile("cp.async.cg.shared.global [%0], [%1], 16;" :: "r"(dst), "l"(src) : "memory");
}
__device__ __forceinline__ void cp_commit() {
    asm volatile("cp.async.commit_group;" ::: "memory");
}
__device__ __forceinline__ void cp_wait7() {
    asm volatile("cp.async.wait_group 7;" ::: "memory");
}
__device__ __forceinline__ void ldsm4(unsigned r[4], unsigned addr) {
    asm volatile("ldmatrix.sync.aligned.m8n8.x4.shared.b16 {%0,%1,%2,%3}, [%4];"
        : "=r"(r[0]), "=r"(r[1]), "=r"(r[2]), "=r"(r[3]) : "r"(addr));
}
__device__ __forceinline__ void ldsm2(unsigned r[2], unsigned addr) {
    asm volatile("ldmatrix.sync.aligned.m8n8.x2.shared.b16 {%0,%1}, [%2];"
        : "=r"(r[0]), "=r"(r[1]) : "r"(addr));
}
__device__ __forceinline__ void mma_bf16(float d[4], const unsigned a[4], unsigned b0, unsigned b1) {
    asm volatile("mma.sync.aligned.m16n8k16.row.col.f32.bf16.bf16.f32 "
        "{%0,%1,%2,%3}, {%4,%5,%6,%7}, {%8,%9}, {%0,%1,%2,%3};"
        : "+f"(d[0]), "+f"(d[1]), "+f"(d[2]), "+f"(d[3])
        : "r"(a[0]), "r"(a[1]), "r"(a[2]), "r"(a[3]), "r"(b0), "r"(b1));
}
__device__ __forceinline__ void mma_f16(float d[4], const unsigned a[4], unsigned b0, unsigned b1) {
    asm volatile("mma.sync.aligned.m16n8k16.row.col.f32.f16.f16.f32 "
        "{%0,%1,%2,%3}, {%4,%5,%6,%7}, {%8,%9}, {%0,%1,%2,%3};"
        : "+f"(d[0]), "+f"(d[1]), "+f"(d[2]), "+f"(d[3])
        : "r"(a[0]), "r"(a[1]), "r"(a[2]), "r"(a[3]), "r"(b0), "r"(b1));
}
__device__ __forceinline__ unsigned packbf2(__nv_bfloat16 a, __nv_bfloat16 b) {
    return ((unsigned)__bfloat16_as_ushort(b) << 16) | (unsigned)__bfloat16_as_ushort(a);
}
__device__ __forceinline__ void split2(float a, float b, unsigned& hw, unsigned& lw) {
    __nv_bfloat16 ha = __float2bfloat16(a), hb = __float2bfloat16(b);
    __nv_bfloat16 la = __float2bfloat16(a - __bfloat162float(ha));
    __nv_bfloat16 lb = __float2bfloat16(b - __bfloat162float(hb));
    hw = packbf2(ha, hb);
    lw = packbf2(la, lb);
}
__device__ __forceinline__ void split_sts16(char* hi_dst, char* lo_dst, const float4 f[4]) {
    unsigned hw[8], lw[8];
#pragma unroll
    for (int i = 0; i < 4; ++i) {
        split2(f[i].x, f[i].y, hw[2 * i], lw[2 * i]);
        split2(f[i].z, f[i].w, hw[2 * i + 1], lw[2 * i + 1]);
    }
    *(uint4*)hi_dst        = make_uint4(hw[0], hw[1], hw[2], hw[3]);
    *(uint4*)(hi_dst + 16) = make_uint4(hw[4], hw[5], hw[6], hw[7]);
    *(uint4*)lo_dst        = make_uint4(lw[0], lw[1], lw[2], lw[3]);
    *(uint4*)(lo_dst + 16) = make_uint4(lw[4], lw[5], lw[6], lw[7]);
}
__device__ __forceinline__ unsigned h2_bits(__half2 v) {
    return *reinterpret_cast<unsigned*>(&v);
}
__device__ __forceinline__ float sigm_f(float x) { return __fdividef(1.0f, 1.0f + __expf(-x)); }
__device__ __forceinline__ float tanh_f(float x) {
    return 1.0f - __fdividef(2.0f, __expf(2.0f * x) + 1.0f);
}

// ---------- prep kernels ----------
__global__ void gather_kernel(const int* __restrict__ inputs, const float* __restrict__ embed) {
    int gid = blockIdx.x * blockDim.x + threadIdx.x;
    const int total4 = SS * BB * (EE / 4);
    if (gid >= total4) return;
    int t = gid / (BB * (EE / 4));
    int r = gid - t * (BB * (EE / 4));
    int m = r / (EE / 4);
    int q = r - m * (EE / 4);
    int tok = inputs[m * SS + t];
    ((float4*)g_Xe)[gid] = ((const float4*)embed)[(size_t)tok * (EE / 4) + q];
}
__global__ void pack_bias(const float* __restrict__ b_ih, const float* __restrict__ b_hh) {
    int idx = blockIdx.x * blockDim.x + threadIdx.x;
    if (idx >= 3 * HH) return;
    int g = idx >> 10, j = idx & 1023;
    int row = c_blk[g] * HH + j;
    g_biasp[idx] = b_ih[row] + b_hh[row];
}
__global__ void zero_h() {
    int i = blockIdx.x * blockDim.x + threadIdx.x;
    if (i < BB * HH) g_h[0][i] = __ushort_as_half((unsigned short)0);
}

// ---------- precompute: g_xpart[t][m][ng] = x_t @ W_ih^T + bias (bf16 3-pass) ----------
__global__ void __launch_bounds__(256, 1) precompute_kernel(const float* __restrict__ W_ih) {
    extern __shared__ __align__(16) char smem[];
    const unsigned sb = smem_u32(smem);
    const int tid = threadIdx.x;
    const int lane = tid & 31;
    const int wid = tid >> 5;
    const int wm = wid & 3, wn = wid >> 2;
    const int jb = blockIdx.x;
    const int t = blockIdx.y;
    const int grp = lane >> 3, r = lane & 7;

    const bool isW = tid < PC_N;
    const bool isA = tid >= 128;
    const float* wptr = nullptr;
    if (isW) {
        int g = tid >> 6, jj = tid & 63;
        wptr = W_ih + (size_t)(c_blk[g] * HH + jb * PC_JT + jj) * EE;
    }
    const float* aptr = isA ? (g_Xe + ((size_t)t * BB + (tid - 128)) * EE) : nullptr;

    unsigned aoffP[2], b4offP;
#pragma unroll
    for (int tt = 0; tt < 2; ++tt)
        aoffP[tt] = PC_AH + (unsigned)((wm * 32 + tt * 16 + (grp & 1) * 8 + r) * 48 + (grp >> 1) * 16);
    b4offP = PC_WH + (unsigned)((wn * 96 + (grp >> 1) * 8 + r) * 48 + (grp & 1) * 16);

    float acc[2][12][4];
#pragma unroll
    for (int a = 0; a < 2; ++a)
#pragma unroll
        for (int j = 0; j < 12; ++j)
#pragma unroll
            for (int q = 0; q < 4; ++q) acc[a][j][q] = 0.0f;

    float4 wreg[4], areg[4];
    if (isW) { const float4* p = (const float4*)(wptr); wreg[0]=p[0]; wreg[1]=p[1]; wreg[2]=p[2]; wreg[3]=p[3]; }
    if (isA) { const float4* p = (const float4*)(aptr); areg[0]=p[0]; areg[1]=p[1]; areg[2]=p[2]; areg[3]=p[3]; }
    {
        char* slot0 = smem;
        if (isW) split_sts16(slot0 + PC_WH + tid * 48, slot0 + PC_WL + tid * 48, wreg);
        if (isA) split_sts16(slot0 + PC_AH + (tid - 128) * 48, slot0 + PC_AL + (tid - 128) * 48, areg);
    }
    __syncthreads();

    for (int c = 0; c < EE / 16; ++c) {
        if (c < EE / 16 - 1) {
            if (isW) { const float4* p = (const float4*)(wptr + (c + 1) * 16); wreg[0]=p[0]; wreg[1]=p[1]; wreg[2]=p[2]; wreg[3]=p[3]; }
            if (isA) { const float4* p = (const float4*)(aptr + (c + 1) * 16); areg[0]=p[0]; areg[1]=p[1]; areg[2]=p[2]; areg[3]=p[3]; }
        }
        unsigned sbase = sb + (unsigned)(c & 1) * PC_SLOT;
        unsigned Ah[2][4], Al[2][4];
#pragma unroll
        for (int tt = 0; tt < 2; ++tt) {
            ldsm4(Ah[tt], sbase + aoffP[tt]);
            ldsm4(Al[tt], sbase + aoffP[tt] + (PC_AL - PC_AH));
        }
#pragma unroll
        for (int p = 0; p < 6; ++p) {
            unsigned Bh[4], Bl[4];
            ldsm4(Bh, sbase + b4offP + (unsigned)p * 768);
            ldsm4(Bl, sbase + b4offP + (unsigned)p * 768 + PC_WL);
#pragma unroll
            for (int tt = 0; tt < 2; ++tt) {
#pragma unroll
                for (int jj = 0; jj < 2; ++jj) {
                    int j = p * 2 + jj;
                    mma_bf16(acc[tt][j], Ah[tt], Bh[2 * jj], Bh[2 * jj + 1]);
                    mma_bf16(acc[tt][j], Ah[tt], Bl[2 * jj], Bl[2 * jj + 1]);
                    mma_bf16(acc[tt][j], Al[tt], Bh[2 * jj], Bh[2 * jj + 1]);
                }
            }
        }
        if (c < EE / 16 - 1) {
            char* slot = smem + ((c + 1) & 1) * PC_SLOT;
            if (isW) split_sts16(slot + PC_WH + tid * 48, slot + PC_WL + tid * 48, wreg);
            if (isA) split_sts16(slot + PC_AH + (tid - 128) * 48, slot + PC_AL + (tid - 128) * 48, areg);
        }
        __syncthreads();
    }

    const int mrow = lane >> 2, nc = (lane & 3) * 2;
#pragma unroll
    for (int tt = 0; tt < 2; ++tt) {
#pragma unroll
        for (int j = 0; j < 12; ++j) {
            int np = wn * 96 + j * 8 + nc;
            int g = np >> 6, jj = np & 63;
            int ng = g * HH + jb * PC_JT + jj;
            float2 bv = *(const float2*)&g_biasp[ng];
            int m = wm * 32 + tt * 16 + mrow;
            float* o0 = g_xpart + ((size_t)t * BB + m) * (3 * HH) + ng;
            *(float2*)o0 = make_float2(acc[tt][j][0] + bv.x, acc[tt][j][1] + bv.y);
            *(float2*)(o0 + (size_t)8 * (3 * HH)) =
                make_float2(acc[tt][j][2] + bv.x, acc[tt][j][3] + bv.y);
        }
    }
}

// ---------- grid barrier (128 CTAs) ----------
__device__ __forceinline__ void grid_barrier() {
    __syncthreads();
    if (threadIdx.x == 0) {
        __threadfence();
        unsigned my = g_gen;
        unsigned t = atomicAdd(&g_count, 1u);
        if (t == RC_NCTA - 1u) {
            atomicExch(&g_count, 0u);
            __threadfence();
            g_gen = my + 1u;
        } else {
            while (g_gen == my) { __nanosleep(32); }
        }
        __threadfence();
    }
    __syncthreads();
}

// ---------- persistent recurrent kernel: fp16, cp.async depth-8 ring ----------
__global__ void __launch_bounds__(256, 1) lstm_rec_kernel(const float* __restrict__ W_hh,
                                                          float* __restrict__ out) {
    extern __shared__ __align__(16) char smem[];
    const unsigned sb = smem_u32(smem);
    const int tid = threadIdx.x;
    const int lane = tid & 31;
    const int w = tid >> 5;            // warp 0..7, owns m rows w*16..w*16+15
    const int cta = blockIdx.x;
    const int j0 = cta * RC_JT;
    const int grp = lane >> 3, r = lane & 7;

    // ---- prologue: W_hh fp16 resident in SMEM (24 n-rows x 1024 k) ----
    {
        const float4* Wv = (const float4*)W_hh;
        for (int i = tid; i < 24 * 256; i += 256) {
            int n = i >> 8;            // 0..23 = g*8+jj
            int kq = i & 255;
            int g = n >> 3, jj = n & 7;
            int rowg = c_blk[g] * HH + cta * RC_JT + jj;
            float4 v = Wv[(size_t)rowg * (HH / 4) + kq];
            __half2 h0 = __floats2half2_rn(v.x, v.y);
            __half2 h1 = __floats2half2_rn(v.z, v.w);
            char* d = smem + n * WS_STRIDE + kq * 8;
            *(__half2*)d = h0;
            *(__half2*)(d + 4) = h1;
        }
    }

    // A-slot lane geometry: row (lane>>1) stride 80B, 32B half (lane&1)
    const unsigned aw = sb + AW_BASE + (unsigned)w * AW_WARP;
    const unsigned cp_dst = aw + (unsigned)((lane >> 1) * 80 + (lane & 1) * 32);
    // ldmatrix offsets within a slot, per k16 half u
    unsigned aoff[2];
#pragma unroll
    for (int u = 0; u < 2; ++u)
        aoff[u] = (unsigned)(((grp & 1) * 8 + r) * 80 + u * 32 + (grp >> 1) * 16);
    const unsigned b4off = (unsigned)(((grp >> 1) * 8 + r) * WS_STRIDE + (grp & 1) * 16);
    const int l2 = lane & 15;
    const unsigned b2off = (unsigned)((16 + (l2 & 7)) * WS_STRIDE + (l2 >> 3) * 16);

    // epilogue mapping
    const int em = tid >> 1;
    const int ej = (tid & 1) * 4;
    float* Gs = (float*)(smem + GS_OFF);

    __syncthreads();   // W resident for all warps

    for (int t = 0; t < SS; ++t) {
        const __half* __restrict__ hs = g_h[t & 1];

        // xpart prefetch (consumed in epilogue)
        const float* xpm = g_xpart + ((size_t)t * BB + em) * (3 * HH) + j0 + ej;
        float4 xi = __ldcg((const float4*)(xpm));
        float4 xg = __ldcg((const float4*)(xpm + HH));
        float4 xo = __ldcg((const float4*)(xpm + 2 * HH));

        float acc[3][4];
#pragma unroll
        for (int j = 0; j < 3; ++j)
#pragma unroll
            for (int q = 0; q < 4; ++q) acc[j][q] = 0.0f;

        // this thread's h stream: row w*16 + (lane>>1), 32B half (lane&1)
        const __half* abase = hs + (size_t)(w * 16 + (lane >> 1)) * HH + (lane & 1) * 16;

        // fill the 8-deep ring (chunks 0..7)
#pragma unroll
        for (int s = 0; s < A_DEPTH; ++s) {
            const __half* src = abase + s * 32;
            unsigned d = cp_dst + (unsigned)s * A_SLOT;
            cp16(d, src);
            cp16(d + 16, src + 8);
            cp_commit();
        }

        for (int c = 0; c < HH / 32; ++c) {
            cp_wait7();          // chunk c landed
            __syncwarp();
            unsigned ab = aw + (unsigned)(c & 7) * A_SLOT;
#pragma unroll
            for (int u = 0; u < 2; ++u) {
                unsigned Af[4], Bh[4], B2[2];
                ldsm4(Af, ab + aoff[u]);
                unsigned wb = sb + (unsigned)(2 * c + u) * 32;
                ldsm4(Bh, wb + b4off);
                ldsm2(B2, wb + b2off);
                mma_f16(acc[0], Af, Bh[0], Bh[1]);
                mma_f16(acc[1], Af, Bh[2], Bh[3]);
                mma_f16(acc[2], Af, B2[0], B2[1]);
            }
            __syncwarp();        // all lanes done reading slot before refill
            if (c + A_DEPTH < HH / 32) {
                const __half* src = abase + (c + A_DEPTH) * 32;
                unsigned d = cp_dst + (unsigned)(c & 7) * A_SLOT;
                cp16(d, src);
                cp16(d + 16, src + 8);
            }
            cp_commit();         // commit every iter (possibly empty) to keep group count aligned
        }

        // exchange gates via SMEM
        {
            const int mrow = lane >> 2, nc = (lane & 3) * 2;
#pragma unroll
            for (int j = 0; j < 3; ++j) {
                int m0 = w * 16 + mrow;
                int n = j * 8 + nc;
                Gs[m0 * GS_STRIDE + n]           = acc[j][0];
                Gs[m0 * GS_STRIDE + n + 1]       = acc[j][1];
                Gs[(m0 + 8) * GS_STRIDE + n]     = acc[j][2];
                Gs[(m0 + 8) * GS_STRIDE + n + 1] = acc[j][3];
            }
        }
        __syncthreads();

        // epilogue: h = sigmoid(o) * tanh( sigmoid(i) * tanh(g) )  (cell carry is zero)
        {
            const float* gsm = Gs + em * GS_STRIDE + ej;
            float xiv[4] = {xi.x, xi.y, xi.z, xi.w};
            float xgv[4] = {xg.x, xg.y, xg.z, xg.w};
            float xov[4] = {xo.x, xo.y, xo.z, xo.w};
            float hv[4];
#pragma unroll
            for (int q = 0; q < 4; ++q) {
                float iv = gsm[q]      + xiv[q];
                float gv = gsm[8 + q]  + xgv[q];
                float ov = gsm[16 + q] + xov[q];
                float ct = sigm_f(iv) * tanh_f(gv);
                hv[q] = sigm_f(ov) * tanh_f(ct);
            }
            __half2 p0 = __floats2half2_rn(hv[0], hv[1]);
            __half2 p1 = __floats2half2_rn(hv[2], hv[3]);
            *(uint2*)(g_h[(t + 1) & 1] + (size_t)em * HH + j0 + ej) =
                make_uint2(h2_bits(p0), h2_bits(p1));
            if (t == SS - 1)
                *(float4*)(out + (size_t)em * HH + j0 + ej) =
                    make_float4(hv[0], hv[1], hv[2], hv[3]);
        }

        grid_barrier();
    }
}

// ---------- launch ----------
extern "C" void kernel_launch(void* const* d_in, const int* in_sizes, int n_in,
                              void* d_out, int out_size) {
    const int*   inputs = (const int*)  d_in[0];
    const float* embed  = (const float*)d_in[1];
    const float* W_ih   = (const float*)d_in[2];
    const float* W_hh   = (const float*)d_in[3];
    const float* b_ih   = (const float*)d_in[4];
    const float* b_hh   = (const float*)d_in[5];
    float* out = (float*)d_out;

    static int attr_done = 0;
    if (!attr_done) {
        cudaFuncSetAttribute(precompute_kernel, cudaFuncAttributeMaxDynamicSharedMemorySize, PC_DSMEM);
        cudaFuncSetAttribute(lstm_rec_kernel,  cudaFuncAttributeMaxDynamicSharedMemorySize, RC_DSMEM);
        attr_done = 1;
    }

    const int total4 = SS * BB * (EE / 4);
    gather_kernel<<<(total4 + 255) / 256, 256>>>(inputs, embed);
    pack_bias<<<(3 * HH + 255) / 256, 256>>>(b_ih, b_hh);
    zero_h<<<(BB * HH + 255) / 256, 256>>>();

    dim3 pgrid(PC_JB, SS);
    precompute_kernel<<<pgrid, 256, PC_DSMEM>>>(W_ih);

    lstm_rec_kernel<<<RC_NCTA, 256, RC_DSMEM>>>(W_hh, out);
}